// round 9
// baseline (speedup 1.0000x reference)
#include <cuda_runtime.h>
#include <cuda_bf16.h>
#include <math.h>
#include <stdint.h>

#define Bb 2
#define Ss 2048
#define Ee 1024
#define Hh 16
#define Dd 64
#define Mm (Bb*Ss)   // 4096

// Scratch (allocation-free rule: __device__ globals)
__device__ float g_q[Bb*Hh*Ss*Dd];
__device__ float g_k[Bb*Hh*Ss*Dd];
__device__ float g_v[Bb*Hh*Ss*Dd];
__device__ float g_ao[Bb*Ss*Ee];
__device__ float g_cos[Ss*32];
__device__ float g_sin[Ss*32];
__device__ __nv_bfloat16 g_xh[Mm*Ee];
__device__ __nv_bfloat16 g_xl[Mm*Ee];
__device__ __nv_bfloat16 g_wh[Ee*Ee];
__device__ __nv_bfloat16 g_wl[Ee*Ee];
__device__ __nv_bfloat16 g_qh[Bb*Hh*Ss*Dd];
__device__ __nv_bfloat16 g_ql[Bb*Hh*Ss*Dd];
__device__ __nv_bfloat16 g_kh[Bb*Hh*Ss*Dd];
__device__ __nv_bfloat16 g_kl[Bb*Hh*Ss*Dd];
__device__ __nv_bfloat16 g_vth[Bb*Hh*Dd*Ss];
__device__ __nv_bfloat16 g_vtl[Bb*Hh*Dd*Ss];

// ---------------------------------------------------------------------------
// Helpers (plain sm_80-class PTX only: mma.sync / ldmatrix / cp.async)
// ---------------------------------------------------------------------------
__device__ __forceinline__ uint32_t smem_to_u32(const void* p) {
    uint32_t a;
    asm("{ .reg .u64 t; cvta.to.shared.u64 t, %1; cvt.u32.u64 %0, t; }" : "=r"(a) : "l"(p));
    return a;
}
#define CP_ASYNC16(dst, src) \
    asm volatile("cp.async.cg.shared.global [%0], [%1], 16;" :: "r"(dst), "l"(src))
#define CP_ASYNC_COMMIT() asm volatile("cp.async.commit_group;" ::: "memory")
#define CP_ASYNC_WAIT0()  asm volatile("cp.async.wait_group 0;" ::: "memory")
#define CP_ASYNC_WAIT1()  asm volatile("cp.async.wait_group 1;" ::: "memory")
#define SWZ128(o) ((o) ^ (((o) >> 3) & 0x70))
#define SWZ64(o)  ((o) ^ (((o) >> 3) & 0x30))

#define LDSM4(r, addr) \
    asm volatile("ldmatrix.sync.aligned.m8n8.x4.shared.b16 {%0,%1,%2,%3}, [%4];" \
        : "=r"((r)[0]), "=r"((r)[1]), "=r"((r)[2]), "=r"((r)[3]) : "r"(addr))

#define MMA16816(c, a, b0, b1) \
    asm volatile("mma.sync.aligned.m16n8k16.row.col.f32.bf16.bf16.f32 " \
        "{%0,%1,%2,%3},{%4,%5,%6,%7},{%8,%9},{%0,%1,%2,%3};" \
        : "+f"((c)[0]), "+f"((c)[1]), "+f"((c)[2]), "+f"((c)[3]) \
        : "r"((a)[0]), "r"((a)[1]), "r"((a)[2]), "r"((a)[3]), "r"(b0), "r"(b1))

__device__ __forceinline__ uint32_t bf2pack(float lo, float hi) {
    uint32_t r;
    asm("cvt.rn.bf16x2.f32 %0, %1, %2;" : "=r"(r) : "f"(hi), "f"(lo));
    return r;
}

// fast e^x on FMA pipe
__device__ __forceinline__ float fexp(float x) {
    x = fmaxf(x, -87.0f);
    float z = x * 1.4426950408889634f;
    float t = z + 12582912.0f;
    float n = t - 12582912.0f;
    float f = z - n;
    float p = 1.3333558146e-3f;
    p = fmaf(p, f, 9.6181291907e-3f);
    p = fmaf(p, f, 5.5504108664e-2f);
    p = fmaf(p, f, 2.4022650696e-1f);
    p = fmaf(p, f, 6.9314718056e-1f);
    p = fmaf(p, f, 1.0f);
    float sc = __uint_as_float((__float_as_uint(t) << 23) + 0x3F800000u);
    return p * sc;
}

// ---------------------------------------------------------------------------
// Split fp32 -> (hi, lo) bf16.
// ---------------------------------------------------------------------------
__global__ __launch_bounds__(256)
void split_kernel(const float* __restrict__ x, __nv_bfloat16* __restrict__ hi,
                  __nv_bfloat16* __restrict__ lo)
{
    int i = blockIdx.x * 256 + threadIdx.x;
    float4 v = ((const float4*)x)[i];
    uint32_t h01 = bf2pack(v.x, v.y), h23 = bf2pack(v.z, v.w);
    float f0 = __uint_as_float(h01 << 16), f1 = __uint_as_float(h01 & 0xFFFF0000u);
    float f2 = __uint_as_float(h23 << 16), f3 = __uint_as_float(h23 & 0xFFFF0000u);
    uint32_t l01 = bf2pack(v.x - f0, v.y - f1), l23 = bf2pack(v.z - f2, v.w - f3);
    ((uint2*)hi)[i] = make_uint2(h01, h23);
    ((uint2*)lo)[i] = make_uint2(l01, l23);
}

// ---------------------------------------------------------------------------
// HMMA GEMM, double-buffered. K-chunk 32 (64B rows, SW64), 2 stages x 32KB.
// CTA tile 128x128. 8 warps 2x4, warp tile 64x32.
// ---------------------------------------------------------------------------
#define TG_SMEM 65536

__global__ __launch_bounds__(256, 2)
void tgemm(const __nv_bfloat16* __restrict__ Ahp, const __nv_bfloat16* __restrict__ Alp,
           const __nv_bfloat16* __restrict__ Bhp, const __nv_bfloat16* __restrict__ Blp,
           const float* __restrict__ bias, float* __restrict__ out, int mode)
{
    extern __shared__ char smem[];
    uint32_t sb = smem_to_u32(smem);
    const int tid = threadIdx.x;
    const int lane = tid & 31, wid = tid >> 5;
    const int m0 = blockIdx.y * 128, n0 = blockIdx.x * 128;
    const int wm = (wid >> 2) * 64, wn = (wid & 3) * 32;

    const char* srcs[4] = {(const char*)Ahp, (const char*)Alp,
                           (const char*)Bhp, (const char*)Blp};
    const int r0s[4] = {m0, m0, n0, n0};

    // fill lambda: chunk kc -> stage st
    auto fill = [&](int kc, int st) {
        uint32_t base = sb + (uint32_t)st * 32768;
        #pragma unroll
        for (int arr = 0; arr < 4; arr++) {
            #pragma unroll
            for (int i = 0; i < 2; i++) {
                int p = i * 256 + tid;
                int r = p >> 2, c = (p & 3) * 16;
                uint32_t dst = base + arr * 8192 + SWZ64((uint32_t)(r * 64 + c));
                const char* src = srcs[arr] + ((size_t)(r0s[arr] + r)) * 2048
                                  + kc * 64 + c;
                CP_ASYNC16(dst, src);
            }
        }
        CP_ASYNC_COMMIT();
    };

    float acc[4][4][4];
    #pragma unroll
    for (int mt = 0; mt < 4; mt++)
        #pragma unroll
        for (int nt = 0; nt < 4; nt++)
            #pragma unroll
            for (int r = 0; r < 4; r++) acc[mt][nt][r] = 0.f;

    // ldmatrix addressing (64B rows, SW64)
    const int lr = lane & 15;
    const uint32_t akb = (uint32_t)(lane >> 4) * 16;
    const uint32_t xrA = (uint32_t)((lr >> 1) & 3) << 4;
    const int brow = (lane & 7) + ((lane >> 1) & 8);
    const uint32_t bkb = (uint32_t)(lane & 8) * 2;
    const uint32_t xrB = (uint32_t)((brow >> 1) & 3) << 4;

    uint32_t aoff[4], boff[2];
    #pragma unroll
    for (int mt = 0; mt < 4; mt++) aoff[mt] = (uint32_t)(wm + mt * 16 + lr) * 64;
    #pragma unroll
    for (int h = 0; h < 2; h++)    boff[h]  = (uint32_t)(wn + h * 16 + brow) * 64;

    fill(0, 0);

    for (int kc = 0; kc < 32; kc++) {
        if (kc < 31) { fill(kc + 1, (kc + 1) & 1); CP_ASYNC_WAIT1(); }
        else         { CP_ASYNC_WAIT0(); }
        __syncthreads();

        const uint32_t base = sb + (uint32_t)(kc & 1) * 32768;
        const uint32_t sA  = base,          sAl = base + 8192;
        const uint32_t sB  = base + 16384,  sBl = base + 24576;

        #pragma unroll
        for (int s = 0; s < 2; s++) {
            const uint32_t kA = ((uint32_t)(s * 32) + akb) ^ xrA;
            const uint32_t kB = ((uint32_t)(s * 32) + bkb) ^ xrB;

            uint32_t ah[4][4], bh[2][4];
            #pragma unroll
            for (int mt = 0; mt < 4; mt++) LDSM4(ah[mt], sA + aoff[mt] + kA);
            #pragma unroll
            for (int h = 0; h < 2; h++)    LDSM4(bh[h],  sB + boff[h] + kB);

            #pragma unroll
            for (int mt = 0; mt < 4; mt++)
                #pragma unroll
                for (int nt = 0; nt < 4; nt++)
                    MMA16816(acc[mt][nt], ah[mt], bh[nt>>1][(nt&1)*2], bh[nt>>1][(nt&1)*2+1]);

            {
                uint32_t al[4][4];
                #pragma unroll
                for (int mt = 0; mt < 4; mt++) LDSM4(al[mt], sAl + aoff[mt] + kA);
                #pragma unroll
                for (int mt = 0; mt < 4; mt++)
                    #pragma unroll
                    for (int nt = 0; nt < 4; nt++)
                        MMA16816(acc[mt][nt], al[mt], bh[nt>>1][(nt&1)*2], bh[nt>>1][(nt&1)*2+1]);
            }
            {
                uint32_t bl[2][4];
                #pragma unroll
                for (int h = 0; h < 2; h++) LDSM4(bl[h], sBl + boff[h] + kB);
                #pragma unroll
                for (int mt = 0; mt < 4; mt++)
                    #pragma unroll
                    for (int nt = 0; nt < 4; nt++)
                        MMA16816(acc[mt][nt], ah[mt], bl[nt>>1][(nt&1)*2], bl[nt>>1][(nt&1)*2+1]);
            }
        }
        __syncthreads();
    }

    const int g = lane >> 2, t = (lane & 3) * 2;
    #pragma unroll
    for (int mt = 0; mt < 4; mt++) {
        #pragma unroll
        for (int nt = 0; nt < 4; nt++) {
            int m = m0 + wm + mt * 16 + g;
            int n = n0 + wn + nt * 8 + t;
            float b0v = bias[n], b1v = bias[n + 1];
            #pragma unroll
            for (int rr = 0; rr < 2; rr++) {
                int mr = m + rr * 8;
                float2 val = make_float2(acc[mt][nt][rr*2] + b0v,
                                         acc[mt][nt][rr*2+1] + b1v);
                float* dst;
                if (mode == 0) {
                    dst = out + (size_t)mr * Ee + n;
                } else {
                    int b = mr >> 11, s = mr & 2047;
                    int h = n >> 6, d0 = n & 63;
                    dst = out + (((size_t)(b * Hh + h) * Ss) + s) * Dd + d0;
                }
                *(float2*)dst = val;
            }
        }
    }
}

// ---------------------------------------------------------------------------
// RoPE: table + apply(with bf16 split output)
// ---------------------------------------------------------------------------
__global__ __launch_bounds__(256)
void rope_table_kernel(float* __restrict__ cosT, float* __restrict__ sinT)
{
    int idx = blockIdx.x * 256 + threadIdx.x;
    int j = idx & 31;
    int s = idx >> 5;
    double inv = exp(-((double)(2 * j) / 64.0) * log(10000.0));
    double sd, cd;
    sincos((double)s * inv, &sd, &cd);
    cosT[idx] = (float)cd;
    sinT[idx] = (float)sd;
}

__global__ __launch_bounds__(256)
void rope_apply_split(const float* __restrict__ qp, const float* __restrict__ kp,
                      __nv_bfloat16* __restrict__ qh, __nv_bfloat16* __restrict__ ql,
                      __nv_bfloat16* __restrict__ kh, __nv_bfloat16* __restrict__ kl,
                      const float* __restrict__ cosT, const float* __restrict__ sinT)
{
    int idx = blockIdx.x * 256 + threadIdx.x;
    int jg  = (idx & 7) * 4;
    int row = idx >> 3;
    int s   = row & (Ss - 1);
    const float* src = (blockIdx.y == 0 ? qp : kp) + (size_t)row * Dd;
    __nv_bfloat16* dh = (blockIdx.y == 0 ? qh : kh) + (size_t)row * Dd;
    __nv_bfloat16* dl = (blockIdx.y == 0 ? ql : kl) + (size_t)row * Dd;

    float4 c  = *(const float4*)(cosT + s * 32 + jg);
    float4 sn = *(const float4*)(sinT + s * 32 + jg);
    float4 x1 = *(const float4*)(src + jg);
    float4 x2 = *(const float4*)(src + jg + 32);

    float r1[4], r2[4];
    r1[0] = x1.x*c.x - x2.x*sn.x;  r2[0] = x2.x*c.x + x1.x*sn.x;
    r1[1] = x1.y*c.y - x2.y*sn.y;  r2[1] = x2.y*c.y + x1.y*sn.y;
    r1[2] = x1.z*c.z - x2.z*sn.z;  r2[2] = x2.z*c.z + x1.z*sn.z;
    r1[3] = x1.w*c.w - x2.w*sn.w;  r2[3] = x2.w*c.w + x1.w*sn.w;

    #pragma unroll
    for (int half = 0; half < 2; half++) {
        float* r = half ? r2 : r1;
        int off = jg + half * 32;
        uint32_t h01 = bf2pack(r[0], r[1]), h23 = bf2pack(r[2], r[3]);
        float f0 = __uint_as_float(h01 << 16), f1 = __uint_as_float(h01 & 0xFFFF0000u);
        float f2 = __uint_as_float(h23 << 16), f3 = __uint_as_float(h23 & 0xFFFF0000u);
        uint32_t l01 = bf2pack(r[0]-f0, r[1]-f1), l23 = bf2pack(r[2]-f2, r[3]-f3);
        *(uint32_t*)(dh + off)     = h01;
        *(uint32_t*)(dh + off + 2) = h23;
        *(uint32_t*)(dl + off)     = l01;
        *(uint32_t*)(dl + off + 2) = l23;
    }
}

// ---------------------------------------------------------------------------
// V convert: fp32 [B,H,S,D] -> split bf16 transposed [B,H,D,S]
// ---------------------------------------------------------------------------
__global__ __launch_bounds__(256)
void vconvert(const float* __restrict__ v, __nv_bfloat16* __restrict__ vth,
              __nv_bfloat16* __restrict__ vtl)
{
    __shared__ float sm[64][65];
    const int s0 = blockIdx.x * 64, bh = blockIdx.y;
    const int tid = threadIdx.x;
    const float* src = v + ((size_t)bh * Ss + s0) * Dd;
    #pragma unroll
    for (int i = 0; i < 16; i++) {
        int p = tid + i * 256;
        int r = p >> 6, c = p & 63;
        sm[c][r] = src[(size_t)r * Dd + c];
    }
    __syncthreads();
    #pragma unroll
    for (int i = 0; i < 8; i++) {
        int pp = tid + i * 256;
        int d = pp >> 5, sp = (pp & 31) * 2;
        float v0 = sm[d][sp], v1 = sm[d][sp + 1];
        uint32_t hp = bf2pack(v0, v1);
        float f0 = __uint_as_float(hp << 16), f1 = __uint_as_float(hp & 0xFFFF0000u);
        uint32_t lp = bf2pack(v0 - f0, v1 - f1);
        size_t off = ((size_t)(bh * Dd + d)) * Ss + s0 + sp;
        *(uint32_t*)(vth + off) = hp;
        *(uint32_t*)(vtl + off) = lp;
    }
}

// ---------------------------------------------------------------------------
// Flash attention, HMMA bf16 3-term split, causal, KV double-buffered.
// Block = 128 q rows, 8 warps (warp = m16 x n64). KV tile 64.
// ---------------------------------------------------------------------------
#define FL_SMEM 98304

__global__ __launch_bounds__(256)
void flash_mma(const __nv_bfloat16* __restrict__ qhp, const __nv_bfloat16* __restrict__ qlp,
               const __nv_bfloat16* __restrict__ khp, const __nv_bfloat16* __restrict__ klp,
               const __nv_bfloat16* __restrict__ vthp, const __nv_bfloat16* __restrict__ vtlp,
               float* __restrict__ out)
{
    extern __shared__ char smem[];
    uint32_t sb = smem_to_u32(smem);
    const uint32_t sQh = sb, sQl = sb + 16384;

    const int tid = threadIdx.x, lane = tid & 31, wid = tid >> 5;
    const int qt = (int)gridDim.x - 1 - (int)blockIdx.x;   // heavy tiles first
    const int bh = blockIdx.y;
    const int q0 = qt * 128;
    const int wm = wid * 16;

    const char* gkh_b = (const char*)khp  + ((size_t)bh * Ss) * 128;
    const char* gkl_b = (const char*)klp  + ((size_t)bh * Ss) * 128;
    const char* gvh_b = (const char*)vthp + ((size_t)bh * Dd) * Ss * 2;
    const char* gvl_b = (const char*)vtlp + ((size_t)bh * Dd) * Ss * 2;

    auto fill_kv = [&](int it, int st) {
        uint32_t base = sb + 32768 + (uint32_t)st * 32768;
        const int kv0 = it * 64;
        #pragma unroll
        for (int i = 0; i < 2; i++) {
            int p = i * 256 + tid;
            int r = p >> 3, c = (p & 7) * 16;
            uint32_t o1 = SWZ128((uint32_t)(r * 128 + c));
            CP_ASYNC16(base + o1,         gkh_b + ((size_t)(kv0 + r)) * 128 + c);
            CP_ASYNC16(base + 8192 + o1,  gkl_b + ((size_t)(kv0 + r)) * 128 + c);
            CP_ASYNC16(base + 16384 + o1, gvh_b + (size_t)r * (Ss * 2) + kv0 * 2 + c);
            CP_ASYNC16(base + 24576 + o1, gvl_b + (size_t)r * (Ss * 2) + kv0 * 2 + c);
        }
        CP_ASYNC_COMMIT();
    };

    // prologue: Q + KV0 in one group
    {
        const char* gq  = (const char*)qhp + ((size_t)(bh * Ss + q0)) * 128;
        const char* gql = (const char*)qlp + ((size_t)(bh * Ss + q0)) * 128;
        #pragma unroll
        for (int i = 0; i < 4; i++) {
            int p = i * 256 + tid;
            int r = p >> 3, c = (p & 7) * 16;
            uint32_t o1 = SWZ128((uint32_t)(r * 128 + c));
            CP_ASYNC16(sQh + o1, gq  + (size_t)r * 128 + c);
            CP_ASYNC16(sQl + o1, gql + (size_t)r * 128 + c);
        }
        fill_kv(0, 0);
    }

    const uint32_t xr  = (uint32_t)(lane & 7) << 4;
    const uint32_t akb = (uint32_t)(lane >> 4) * 16;
    const uint32_t arow = (uint32_t)(wm + (lane & 15)) * 128;
    uint32_t aQh[4][4], aQl[4][4];

    const int brow = (lane & 7) + ((lane >> 1) & 8);
    const uint32_t bkb = (uint32_t)(lane & 8) * 2;
    uint32_t boffs[4];
    #pragma unroll
    for (int p = 0; p < 4; p++) boffs[p] = (uint32_t)(p * 16 + brow) * 128;

    float o[8][4];
    #pragma unroll
    for (int nt = 0; nt < 8; nt++)
        #pragma unroll
        for (int r = 0; r < 4; r++) o[nt][r] = 0.f;
    float mv[2] = {-1e30f, -1e30f}, lv[2] = {0.f, 0.f};

    const int g = lane >> 2, tq = (lane & 3) * 2;
    const int ntiles = 2 * qt + 2;

    for (int it = 0; it < ntiles; it++) {
        if (it + 1 < ntiles) { fill_kv(it + 1, (it + 1) & 1); CP_ASYNC_WAIT1(); }
        else                 { CP_ASYNC_WAIT0(); }
        __syncthreads();

        if (it == 0) {
            #pragma unroll
            for (int s = 0; s < 4; s++) {
                uint32_t kA = ((uint32_t)(s * 32) + akb) ^ xr;
                LDSM4(aQh[s], sQh + arow + kA);
                LDSM4(aQl[s], sQl + arow + kA);
            }
        }

        const uint32_t base = sb + 32768 + (uint32_t)(it & 1) * 32768;
        const uint32_t sKh = base,          sKl = base + 8192;
        const uint32_t sVh = base + 16384,  sVl = base + 24576;
        const int kv0 = it * 64;

        // S = Q K^T (3 terms)
        float acc[8][4];
        #pragma unroll
        for (int nt = 0; nt < 8; nt++)
            #pragma unroll
            for (int r = 0; r < 4; r++) acc[nt][r] = 0.f;

        #pragma unroll
        for (int s = 0; s < 4; s++) {
            uint32_t kB = ((uint32_t)(s * 32) + bkb) ^ xr;
            uint32_t bKh[4][4], bKl[4][4];
            #pragma unroll
            for (int p = 0; p < 4; p++) LDSM4(bKh[p], sKh + boffs[p] + kB);
            #pragma unroll
            for (int p = 0; p < 4; p++) LDSM4(bKl[p], sKl + boffs[p] + kB);
            #pragma unroll
            for (int p = 0; p < 4; p++) {
                MMA16816(acc[2*p],   aQh[s], bKh[p][0], bKh[p][1]);
                MMA16816(acc[2*p+1], aQh[s], bKh[p][2], bKh[p][3]);
                MMA16816(acc[2*p],   aQl[s], bKh[p][0], bKh[p][1]);
                MMA16816(acc[2*p+1], aQl[s], bKh[p][2], bKh[p][3]);
                MMA16816(acc[2*p],   aQh[s], bKl[p][0], bKl[p][1]);
                MMA16816(acc[2*p+1], aQh[s], bKl[p][2], bKl[p][3]);
            }
        }

        const int row0 = q0 + wm + g;
        if (it >= 2 * qt) {
            #pragma unroll
            for (int nt = 0; nt < 8; nt++) {
                int col = kv0 + nt * 8 + tq;
                #pragma unroll
                for (int r = 0; r < 4; r++) {
                    int cc = col + (r & 1);
                    int rr = row0 + (r >= 2 ? 8 : 0);
                    acc[nt][r] = (cc > rr) ? -1e30f : acc[nt][r] * 0.125f;
                }
            }
        } else {
            #pragma unroll
            for (int nt = 0; nt < 8; nt++)
                #pragma unroll
                for (int r = 0; r < 4; r++) acc[nt][r] *= 0.125f;
        }

        #pragma unroll
        for (int h = 0; h < 2; h++) {
            float rmax = -1e30f;
            #pragma unroll
            for (int nt = 0; nt < 8; nt++)
                rmax = fmaxf(rmax, fmaxf(acc[nt][2*h], acc[nt][2*h+1]));
            rmax = fmaxf(rmax, __shfl_xor_sync(0xffffffffu, rmax, 1));
            rmax = fmaxf(rmax, __shfl_xor_sync(0xffffffffu, rmax, 2));
            float mnew = fmaxf(mv[h], rmax);
            float fac = fexp(mv[h] - mnew);
            float rs = 0.f;
            #pragma unroll
            for (int nt = 0; nt < 8; nt++) {
                acc[nt][2*h]   = fexp(acc[nt][2*h]   - mnew);
                acc[nt][2*h+1] = fexp(acc[nt][2*h+1] - mnew);
                rs += acc[nt][2*h] + acc[nt][2*h+1];
            }
            rs += __shfl_xor_sync(0xffffffffu, rs, 1);
            rs += __shfl_xor_sync(0xffffffffu, rs, 2);
            lv[h] = lv[h] * fac + rs;
            mv[h] = mnew;
            #pragma unroll
            for (int nt = 0; nt < 8; nt++) { o[nt][2*h] *= fac; o[nt][2*h+1] *= fac; }
        }

        // P -> split bf16 A-fragments
        uint32_t aPh[4][4], aPl[4][4];
        #pragma unroll
        for (int ks = 0; ks < 4; ks++) {
            #pragma unroll
            for (int half = 0; half < 2; half++) {
                int nt = 2 * ks + half;
                #pragma unroll
                for (int rp = 0; rp < 2; rp++) {
                    float p0 = acc[nt][2*rp], p1 = acc[nt][2*rp+1];
                    uint32_t hp = bf2pack(p0, p1);
                    float f0 = __uint_as_float(hp << 16);
                    float f1 = __uint_as_float(hp & 0xFFFF0000u);
                    uint32_t lp = bf2pack(p0 - f0, p1 - f1);
                    aPh[ks][half*2 + rp] = hp;
                    aPl[ks][half*2 + rp] = lp;
                }
            }
        }

        // O += P V (3 terms)
        #pragma unroll
        for (int s = 0; s < 4; s++) {
            uint32_t kB = ((uint32_t)(s * 32) + bkb) ^ xr;
            uint32_t bVh[4][4], bVl[4][4];
            #pragma unroll
            for (int p = 0; p < 4; p++) LDSM4(bVh[p], sVh + boffs[p] + kB);
            #pragma unroll
            for (int p = 0; p < 4; p++) LDSM4(bVl[p], sVl + boffs[p] + kB);
            #pragma unroll
            for (int p = 0; p < 4; p++) {
                MMA16816(o[2*p],   aPh[s], bVh[p][0], bVh[p][1]);
                MMA16816(o[2*p+1], aPh[s], bVh[p][2], bVh[p][3]);
                MMA16816(o[2*p],   aPl[s], bVh[p][0], bVh[p][1]);
                MMA16816(o[2*p+1], aPl[s], bVh[p][2], bVh[p][3]);
                MMA16816(o[2*p],   aPh[s], bVl[p][0], bVl[p][1]);
                MMA16816(o[2*p+1], aPh[s], bVl[p][2], bVl[p][3]);
            }
        }
        __syncthreads();
    }

    // epilogue
    const int b = bh >> 4, h = bh & 15;
    float il0 = 1.0f / lv[0], il1 = 1.0f / lv[1];
    const int row0 = q0 + wm + g;
    #pragma unroll
    for (int nt = 0; nt < 8; nt++) {
        int col = h * 64 + nt * 8 + tq;
        float2 v0 = make_float2(o[nt][0] * il0, o[nt][1] * il0);
        float2 v1 = make_float2(o[nt][2] * il1, o[nt][3] * il1);
        *(float2*)(out + ((size_t)(b * Ss + row0)) * Ee + col)     = v0;
        *(float2*)(out + ((size_t)(b * Ss + row0 + 8)) * Ee + col) = v1;
    }
}

// ---------------------------------------------------------------------------
extern "C" void kernel_launch(void* const* d_in, const int* in_sizes, int n_in,
                              void* d_out, int out_size)
{
    (void)in_sizes; (void)n_in; (void)out_size;
    const float* query = (const float*)d_in[0];
    const float* key   = (const float*)d_in[1];
    const float* value = (const float*)d_in[2];
    const float* Wq = (const float*)d_in[3];
    const float* bq = (const float*)d_in[4];
    const float* Wk = (const float*)d_in[5];
    const float* bk = (const float*)d_in[6];
    const float* Wv = (const float*)d_in[7];
    const float* bv = (const float*)d_in[8];
    const float* Wo = (const float*)d_in[9];
    const float* bo = (const float*)d_in[10];
    float* out = (float*)d_out;

    float *qp, *kp, *vp, *aop, *ct, *st;
    __nv_bfloat16 *xh, *xl, *wh, *wl, *qh, *ql, *kh, *kl, *vth, *vtl;
    cudaGetSymbolAddress((void**)&qp,  g_q);
    cudaGetSymbolAddress((void**)&kp,  g_k);
    cudaGetSymbolAddress((void**)&vp,  g_v);
    cudaGetSymbolAddress((void**)&aop, g_ao);
    cudaGetSymbolAddress((void**)&ct,  g_cos);
    cudaGetSymbolAddress((void**)&st,  g_sin);
    cudaGetSymbolAddress((void**)&xh,  g_xh);
    cudaGetSymbolAddress((void**)&xl,  g_xl);
    cudaGetSymbolAddress((void**)&wh,  g_wh);
    cudaGetSymbolAddress((void**)&wl,  g_wl);
    cudaGetSymbolAddress((void**)&qh,  g_qh);
    cudaGetSymbolAddress((void**)&ql,  g_ql);
    cudaGetSymbolAddress((void**)&kh,  g_kh);
    cudaGetSymbolAddress((void**)&kl,  g_kl);
    cudaGetSymbolAddress((void**)&vth, g_vth);
    cudaGetSymbolAddress((void**)&vtl, g_vtl);

    cudaFuncSetAttribute(tgemm,
                         cudaFuncAttributeMaxDynamicSharedMemorySize, TG_SMEM);
    cudaFuncSetAttribute(flash_mma,
                         cudaFuncAttributeMaxDynamicSharedMemorySize, FL_SMEM);

    const int WBLK = (Ee * Ee / 4) / 256;   // 1024
    const int XBLK = (Mm * Ee / 4) / 256;   // 4096
    dim3 gg(Ee / 128, Mm / 128);            // (8, 32)

    rope_table_kernel<<<(Ss * 32) / 256, 256>>>(ct, st);

    split_kernel<<<WBLK, 256>>>(Wq, wh, wl);
    split_kernel<<<XBLK, 256>>>(query, xh, xl);
    tgemm<<<gg, 256, TG_SMEM>>>(xh, xl, wh, wl, bq, qp, 1);

    split_kernel<<<WBLK, 256>>>(Wk, wh, wl);
    split_kernel<<<XBLK, 256>>>(key, xh, xl);
    tgemm<<<gg, 256, TG_SMEM>>>(xh, xl, wh, wl, bk, kp, 1);

    split_kernel<<<WBLK, 256>>>(Wv, wh, wl);
    split_kernel<<<XBLK, 256>>>(value, xh, xl);
    tgemm<<<gg, 256, TG_SMEM>>>(xh, xl, wh, wl, bv, vp, 1);

    int ropeBlocks = (Bb * Hh * Ss * 8) / 256;   // 2048
    rope_apply_split<<<dim3(ropeBlocks, 2), 256>>>(qp, kp, qh, ql, kh, kl, ct, st);

    vconvert<<<dim3(Ss / 64, Bb * Hh), 256>>>(vp, vth, vtl);

    flash_mma<<<dim3(Ss / 128, Bb * Hh), 256, FL_SMEM>>>(qh, ql, kh, kl, vth, vtl, aop);

    split_kernel<<<WBLK, 256>>>(Wo, wh, wl);
    split_kernel<<<XBLK, 256>>>(aop, xh, xl);
    tgemm<<<gg, 256, TG_SMEM>>>(xh, xl, wh, wl, bo, out, 0);
}

// round 10
// speedup vs baseline: 1.1045x; 1.1045x over previous
#include <cuda_runtime.h>
#include <cuda_bf16.h>
#include <math.h>
#include <stdint.h>

#define Bb 2
#define Ss 2048
#define Ee 1024
#define Hh 16
#define Dd 64
#define Mm (Bb*Ss)   // 4096

// Scratch (allocation-free rule: __device__ globals)
__device__ float g_q[Bb*Hh*Ss*Dd];
__device__ float g_k[Bb*Hh*Ss*Dd];
__device__ float g_v[Bb*Hh*Ss*Dd];
__device__ float g_ao[Bb*Ss*Ee];
__device__ float g_cos[Ss*32];
__device__ float g_sin[Ss*32];
__device__ __nv_bfloat16 g_xh3[3*Mm*Ee];
__device__ __nv_bfloat16 g_xl3[3*Mm*Ee];
__device__ __nv_bfloat16 g_wh3[3*Ee*Ee];
__device__ __nv_bfloat16 g_wl3[3*Ee*Ee];
__device__ __nv_bfloat16 g_qh[Bb*Hh*Ss*Dd];
__device__ __nv_bfloat16 g_ql[Bb*Hh*Ss*Dd];
__device__ __nv_bfloat16 g_kh[Bb*Hh*Ss*Dd];
__device__ __nv_bfloat16 g_kl[Bb*Hh*Ss*Dd];
__device__ __nv_bfloat16 g_vth[Bb*Hh*Dd*Ss];
__device__ __nv_bfloat16 g_vtl[Bb*Hh*Dd*Ss];

// ---------------------------------------------------------------------------
// Helpers (plain sm_80-class PTX only: mma.sync / ldmatrix / cp.async)
// ---------------------------------------------------------------------------
__device__ __forceinline__ uint32_t smem_to_u32(const void* p) {
    uint32_t a;
    asm("{ .reg .u64 t; cvta.to.shared.u64 t, %1; cvt.u32.u64 %0, t; }" : "=r"(a) : "l"(p));
    return a;
}
#define CP_ASYNC16(dst, src) \
    asm volatile("cp.async.cg.shared.global [%0], [%1], 16;" :: "r"(dst), "l"(src))
#define CP_ASYNC_COMMIT() asm volatile("cp.async.commit_group;" ::: "memory")
#define CP_ASYNC_WAIT0()  asm volatile("cp.async.wait_group 0;" ::: "memory")
#define SWZ128(o) ((o) ^ (((o) >> 3) & 0x70))

#define LDSM4(r, addr) \
    asm volatile("ldmatrix.sync.aligned.m8n8.x4.shared.b16 {%0,%1,%2,%3}, [%4];" \
        : "=r"((r)[0]), "=r"((r)[1]), "=r"((r)[2]), "=r"((r)[3]) : "r"(addr))

#define MMA16816(c, a, b0, b1) \
    asm volatile("mma.sync.aligned.m16n8k16.row.col.f32.bf16.bf16.f32 " \
        "{%0,%1,%2,%3},{%4,%5,%6,%7},{%8,%9},{%0,%1,%2,%3};" \
        : "+f"((c)[0]), "+f"((c)[1]), "+f"((c)[2]), "+f"((c)[3]) \
        : "r"((a)[0]), "r"((a)[1]), "r"((a)[2]), "r"((a)[3]), "r"(b0), "r"(b1))

__device__ __forceinline__ uint32_t bf2pack(float lo, float hi) {
    uint32_t r;
    asm("cvt.rn.bf16x2.f32 %0, %1, %2;" : "=r"(r) : "f"(hi), "f"(lo));
    return r;
}

// fast e^x on FMA pipe
__device__ __forceinline__ float fexp(float x) {
    x = fmaxf(x, -87.0f);
    float z = x * 1.4426950408889634f;
    float t = z + 12582912.0f;
    float n = t - 12582912.0f;
    float f = z - n;
    float p = 1.3333558146e-3f;
    p = fmaf(p, f, 9.6181291907e-3f);
    p = fmaf(p, f, 5.5504108664e-2f);
    p = fmaf(p, f, 2.4022650696e-1f);
    p = fmaf(p, f, 6.9314718056e-1f);
    p = fmaf(p, f, 1.0f);
    float sc = __uint_as_float((__float_as_uint(t) << 23) + 0x3F800000u);
    return p * sc;
}

__device__ __forceinline__ void split4(const float4 v, uint2& h, uint2& l) {
    uint32_t h01 = bf2pack(v.x, v.y), h23 = bf2pack(v.z, v.w);
    float f0 = __uint_as_float(h01 << 16), f1 = __uint_as_float(h01 & 0xFFFF0000u);
    float f2 = __uint_as_float(h23 << 16), f3 = __uint_as_float(h23 & 0xFFFF0000u);
    uint32_t l01 = bf2pack(v.x - f0, v.y - f1), l23 = bf2pack(v.z - f2, v.w - f3);
    h = make_uint2(h01, h23);
    l = make_uint2(l01, l23);
}

// ---------------------------------------------------------------------------
// Batched splits: blockIdx.y selects source 0..2, writes slot y of triple buf.
// ---------------------------------------------------------------------------
__global__ __launch_bounds__(256)
void split3_kernel(const float* __restrict__ s0, const float* __restrict__ s1,
                   const float* __restrict__ s2, __nv_bfloat16* __restrict__ hi,
                   __nv_bfloat16* __restrict__ lo, int elems4)
{
    int z = blockIdx.y;
    const float* x = (z == 0) ? s0 : (z == 1) ? s1 : s2;
    int i = blockIdx.x * 256 + threadIdx.x;
    float4 v = ((const float4*)x)[i];
    uint2 h, l;
    split4(v, h, l);
    ((uint2*)hi)[(size_t)z * elems4 + i] = h;
    ((uint2*)lo)[(size_t)z * elems4 + i] = l;
}

// plain split into slot 0 (for the O projection)
__global__ __launch_bounds__(256)
void split_kernel(const float* __restrict__ x, __nv_bfloat16* __restrict__ hi,
                  __nv_bfloat16* __restrict__ lo)
{
    int i = blockIdx.x * 256 + threadIdx.x;
    float4 v = ((const float4*)x)[i];
    uint2 h, l;
    split4(v, h, l);
    ((uint2*)hi)[i] = h;
    ((uint2*)lo)[i] = l;
}

// ---------------------------------------------------------------------------
// HMMA GEMM body (R8 single-stage, K-chunk 64, SW128, 2 CTAs/SM).
// ---------------------------------------------------------------------------
#define TG_SMEM 65536

__device__ __forceinline__
void tgemm_body(uint32_t sb, const __nv_bfloat16* Ahp, const __nv_bfloat16* Alp,
                const __nv_bfloat16* Bhp, const __nv_bfloat16* Blp,
                const float* bias, float* out, int mode, int m0, int n0)
{
    const int tid = threadIdx.x;
    const int lane = tid & 31, wid = tid >> 5;
    const int wm = (wid >> 2) * 64, wn = (wid & 3) * 32;

    const uint32_t sA  = sb;
    const uint32_t sAl = sb + 16384;
    const uint32_t sB  = sb + 32768;
    const uint32_t sBl = sb + 49152;

    float acc[4][4][4];
    #pragma unroll
    for (int mt = 0; mt < 4; mt++)
        #pragma unroll
        for (int nt = 0; nt < 4; nt++)
            #pragma unroll
            for (int r = 0; r < 4; r++) acc[mt][nt][r] = 0.f;

    const int lr = lane & 15;
    const uint32_t akb = (lane >> 4) * 16;
    const uint32_t xrA = (uint32_t)(lr & 7) << 4;
    const int brow = (lane & 7) + ((lane >> 1) & 8);
    const uint32_t bkb = (uint32_t)(lane & 8) * 2;
    const uint32_t xrB = (uint32_t)(lane & 7) << 4;

    uint32_t aoff[4], boff[2];
    #pragma unroll
    for (int mt = 0; mt < 4; mt++) aoff[mt] = (uint32_t)(wm + mt * 16 + lr) * 128;
    #pragma unroll
    for (int h = 0; h < 2; h++)    boff[h]  = (uint32_t)(wn + h * 16 + brow) * 128;

    const char* srcs[4] = {(const char*)Ahp, (const char*)Alp,
                           (const char*)Bhp, (const char*)Blp};
    const uint32_t dsts[4] = {sA, sAl, sB, sBl};
    const int r0s[4] = {m0, m0, n0, n0};

    for (int kc = 0; kc < 16; kc++) {
        if (kc) __syncthreads();
        #pragma unroll
        for (int arr = 0; arr < 4; arr++) {
            #pragma unroll
            for (int i = 0; i < 4; i++) {
                int p = i * 256 + tid;
                int r = p >> 3, c = (p & 7) * 16;
                uint32_t dst = dsts[arr] + SWZ128((uint32_t)(r * 128 + c));
                const char* src = srcs[arr] + ((size_t)(r0s[arr] + r)) * 2048
                                  + kc * 128 + c;
                CP_ASYNC16(dst, src);
            }
        }
        CP_ASYNC_COMMIT();
        CP_ASYNC_WAIT0();
        __syncthreads();

        #pragma unroll
        for (int s = 0; s < 4; s++) {
            const uint32_t kA = ((uint32_t)(s * 32) + akb) ^ xrA;
            const uint32_t kB = ((uint32_t)(s * 32) + bkb) ^ xrB;

            uint32_t ah[4][4], bh[2][4];
            #pragma unroll
            for (int mt = 0; mt < 4; mt++) LDSM4(ah[mt], sA + aoff[mt] + kA);
            #pragma unroll
            for (int h = 0; h < 2; h++)    LDSM4(bh[h],  sB + boff[h] + kB);

            #pragma unroll
            for (int mt = 0; mt < 4; mt++)
                #pragma unroll
                for (int nt = 0; nt < 4; nt++)
                    MMA16816(acc[mt][nt], ah[mt], bh[nt>>1][(nt&1)*2], bh[nt>>1][(nt&1)*2+1]);

            {
                uint32_t al[4][4];
                #pragma unroll
                for (int mt = 0; mt < 4; mt++) LDSM4(al[mt], sAl + aoff[mt] + kA);
                #pragma unroll
                for (int mt = 0; mt < 4; mt++)
                    #pragma unroll
                    for (int nt = 0; nt < 4; nt++)
                        MMA16816(acc[mt][nt], al[mt], bh[nt>>1][(nt&1)*2], bh[nt>>1][(nt&1)*2+1]);
            }
            {
                uint32_t bl[2][4];
                #pragma unroll
                for (int h = 0; h < 2; h++) LDSM4(bl[h], sBl + boff[h] + kB);
                #pragma unroll
                for (int mt = 0; mt < 4; mt++)
                    #pragma unroll
                    for (int nt = 0; nt < 4; nt++)
                        MMA16816(acc[mt][nt], ah[mt], bl[nt>>1][(nt&1)*2], bl[nt>>1][(nt&1)*2+1]);
            }
        }
    }

    const int g = lane >> 2, t = (lane & 3) * 2;
    #pragma unroll
    for (int mt = 0; mt < 4; mt++) {
        #pragma unroll
        for (int nt = 0; nt < 4; nt++) {
            int m = m0 + wm + mt * 16 + g;
            int n = n0 + wn + nt * 8 + t;
            float b0v = bias[n], b1v = bias[n + 1];
            #pragma unroll
            for (int rr = 0; rr < 2; rr++) {
                int mr = m + rr * 8;
                float2 val = make_float2(acc[mt][nt][rr*2] + b0v,
                                         acc[mt][nt][rr*2+1] + b1v);
                float* dst;
                if (mode == 0) {
                    dst = out + (size_t)mr * Ee + n;
                } else {
                    int b = mr >> 11, s = mr & 2047;
                    int h = n >> 6, d0 = n & 63;
                    dst = out + (((size_t)(b * Hh + h) * Ss) + s) * Dd + d0;
                }
                *(float2*)dst = val;
            }
        }
    }
}

// Fused QKV projection: blockIdx.z picks {X,W,bias,out} set, scatter mode.
__global__ __launch_bounds__(256, 2)
void tgemm_qkv(const float* __restrict__ bq, const float* __restrict__ bk,
               const float* __restrict__ bv, float* __restrict__ qp,
               float* __restrict__ kp, float* __restrict__ vp)
{
    extern __shared__ char smem[];
    uint32_t sb = smem_to_u32(smem);
    const int z = blockIdx.z;
    const float* bias = (z == 0) ? bq : (z == 1) ? bk : bv;
    float* out = (z == 0) ? qp : (z == 1) ? kp : vp;
    const size_t xo = (size_t)z * Mm * Ee, wo = (size_t)z * Ee * Ee;
    tgemm_body(sb, g_xh3 + xo, g_xl3 + xo, g_wh3 + wo, g_wl3 + wo,
               bias, out, 1, blockIdx.y * 128, blockIdx.x * 128);
}

// Generic GEMM (O projection): slot 0 of triple buffers.
__global__ __launch_bounds__(256, 2)
void tgemm_o(const float* __restrict__ bias, float* __restrict__ out)
{
    extern __shared__ char smem[];
    uint32_t sb = smem_to_u32(smem);
    tgemm_body(sb, g_xh3, g_xl3, g_wh3, g_wl3,
               bias, out, 0, blockIdx.y * 128, blockIdx.x * 128);
}

// ---------------------------------------------------------------------------
// RoPE: table + apply(with bf16 split output)
// ---------------------------------------------------------------------------
__global__ __launch_bounds__(256)
void rope_table_kernel(float* __restrict__ cosT, float* __restrict__ sinT)
{
    int idx = blockIdx.x * 256 + threadIdx.x;
    int j = idx & 31;
    int s = idx >> 5;
    double inv = exp(-((double)(2 * j) / 64.0) * log(10000.0));
    double sd, cd;
    sincos((double)s * inv, &sd, &cd);
    cosT[idx] = (float)cd;
    sinT[idx] = (float)sd;
}

__global__ __launch_bounds__(256)
void rope_apply_split(const float* __restrict__ qp, const float* __restrict__ kp,
                      __nv_bfloat16* __restrict__ qh, __nv_bfloat16* __restrict__ ql,
                      __nv_bfloat16* __restrict__ kh, __nv_bfloat16* __restrict__ kl,
                      const float* __restrict__ cosT, const float* __restrict__ sinT)
{
    int idx = blockIdx.x * 256 + threadIdx.x;
    int jg  = (idx & 7) * 4;
    int row = idx >> 3;
    int s   = row & (Ss - 1);
    const float* src = (blockIdx.y == 0 ? qp : kp) + (size_t)row * Dd;
    __nv_bfloat16* dh = (blockIdx.y == 0 ? qh : kh) + (size_t)row * Dd;
    __nv_bfloat16* dl = (blockIdx.y == 0 ? ql : kl) + (size_t)row * Dd;

    float4 c  = *(const float4*)(cosT + s * 32 + jg);
    float4 sn = *(const float4*)(sinT + s * 32 + jg);
    float4 x1 = *(const float4*)(src + jg);
    float4 x2 = *(const float4*)(src + jg + 32);

    float4 r1, r2;
    r1.x = x1.x*c.x - x2.x*sn.x;  r2.x = x2.x*c.x + x1.x*sn.x;
    r1.y = x1.y*c.y - x2.y*sn.y;  r2.y = x2.y*c.y + x1.y*sn.y;
    r1.z = x1.z*c.z - x2.z*sn.z;  r2.z = x2.z*c.z + x1.z*sn.z;
    r1.w = x1.w*c.w - x2.w*sn.w;  r2.w = x2.w*c.w + x1.w*sn.w;

    uint2 h, l;
    split4(r1, h, l);
    *(uint2*)(dh + jg) = h;
    *(uint2*)(dl + jg) = l;
    split4(r2, h, l);
    *(uint2*)(dh + jg + 32) = h;
    *(uint2*)(dl + jg + 32) = l;
}

// ---------------------------------------------------------------------------
// V convert: fp32 [B,H,S,D] -> split bf16 transposed [B,H,D,S]
// ---------------------------------------------------------------------------
__global__ __launch_bounds__(256)
void vconvert(const float* __restrict__ v, __nv_bfloat16* __restrict__ vth,
              __nv_bfloat16* __restrict__ vtl)
{
    __shared__ float sm[64][65];
    const int s0 = blockIdx.x * 64, bh = blockIdx.y;
    const int tid = threadIdx.x;
    const float* src = v + ((size_t)bh * Ss + s0) * Dd;
    #pragma unroll
    for (int i = 0; i < 16; i++) {
        int p = tid + i * 256;
        int r = p >> 6, c = p & 63;
        sm[c][r] = src[(size_t)r * Dd + c];
    }
    __syncthreads();
    #pragma unroll
    for (int i = 0; i < 8; i++) {
        int pp = tid + i * 256;
        int d = pp >> 5, sp = (pp & 31) * 2;
        float v0 = sm[d][sp], v1 = sm[d][sp + 1];
        uint32_t hp = bf2pack(v0, v1);
        float f0 = __uint_as_float(hp << 16), f1 = __uint_as_float(hp & 0xFFFF0000u);
        uint32_t lp = bf2pack(v0 - f0, v1 - f1);
        size_t off = ((size_t)(bh * Dd + d)) * Ss + s0 + sp;
        *(uint32_t*)(vth + off) = hp;
        *(uint32_t*)(vtl + off) = lp;
    }
}

// ---------------------------------------------------------------------------
// Flash attention, HMMA bf16 3-term split, causal (R8 single-stage, 64KB).
// Block = 128 q rows, 8 warps (warp = m16, full kv width 64). KV tile 64.
// ---------------------------------------------------------------------------
#define FL_SMEM 65536

__global__ __launch_bounds__(256)
void flash_mma(const __nv_bfloat16* __restrict__ qhp, const __nv_bfloat16* __restrict__ qlp,
               const __nv_bfloat16* __restrict__ khp, const __nv_bfloat16* __restrict__ klp,
               const __nv_bfloat16* __restrict__ vthp, const __nv_bfloat16* __restrict__ vtlp,
               float* __restrict__ out)
{
    extern __shared__ char smem[];
    uint32_t sb = smem_to_u32(smem);
    const uint32_t sQh = sb,          sQl = sb + 16384;
    const uint32_t sKh = sb + 32768,  sKl = sb + 40960;
    const uint32_t sVh = sb + 49152,  sVl = sb + 57344;

    const int tid = threadIdx.x, lane = tid & 31, wid = tid >> 5;
    const int qt = (int)gridDim.x - 1 - (int)blockIdx.x;   // heavy tiles first
    const int bh = blockIdx.y;
    const int q0 = qt * 128;
    const int wm = wid * 16;

    {
        const char* gq  = (const char*)qhp + ((size_t)(bh * Ss + q0)) * 128;
        const char* gql = (const char*)qlp + ((size_t)(bh * Ss + q0)) * 128;
        #pragma unroll
        for (int i = 0; i < 4; i++) {
            int p = i * 256 + tid;
            int r = p >> 3, c = (p & 7) * 16;
            uint32_t o1 = SWZ128((uint32_t)(r * 128 + c));
            CP_ASYNC16(sQh + o1, gq  + (size_t)r * 128 + c);
            CP_ASYNC16(sQl + o1, gql + (size_t)r * 128 + c);
        }
        CP_ASYNC_COMMIT(); CP_ASYNC_WAIT0();
    }
    __syncthreads();

    const uint32_t xr  = (uint32_t)(lane & 7) << 4;
    const uint32_t akb = (uint32_t)(lane >> 4) * 16;
    const uint32_t arow = (uint32_t)(wm + (lane & 15)) * 128;
    uint32_t aQh[4][4], aQl[4][4];
    #pragma unroll
    for (int s = 0; s < 4; s++) {
        uint32_t kA = ((uint32_t)(s * 32) + akb) ^ xr;
        LDSM4(aQh[s], sQh + arow + kA);
        LDSM4(aQl[s], sQl + arow + kA);
    }

    const int brow = (lane & 7) + ((lane >> 1) & 8);
    const uint32_t bkb = (uint32_t)(lane & 8) * 2;
    uint32_t boffs[4];
    #pragma unroll
    for (int p = 0; p < 4; p++) boffs[p] = (uint32_t)(p * 16 + brow) * 128;

    float o[8][4];
    #pragma unroll
    for (int nt = 0; nt < 8; nt++)
        #pragma unroll
        for (int r = 0; r < 4; r++) o[nt][r] = 0.f;
    float mv[2] = {-1e30f, -1e30f}, lv[2] = {0.f, 0.f};

    const int g = lane >> 2, tq = (lane & 3) * 2;
    const int ntiles = 2 * qt + 2;

    for (int it = 0; it < ntiles; it++) {
        const int kv0 = it * 64;
        __syncthreads();
        {
            const char* gkh = (const char*)khp  + ((size_t)(bh * Ss + kv0)) * 128;
            const char* gkl = (const char*)klp  + ((size_t)(bh * Ss + kv0)) * 128;
            const char* gvh = (const char*)vthp + (((size_t)bh * Dd) * Ss + kv0) * 2;
            const char* gvl = (const char*)vtlp + (((size_t)bh * Dd) * Ss + kv0) * 2;
            #pragma unroll
            for (int i = 0; i < 2; i++) {
                int p = i * 256 + tid;
                int r = p >> 3, c = (p & 7) * 16;
                uint32_t o1 = SWZ128((uint32_t)(r * 128 + c));
                CP_ASYNC16(sKh + o1, gkh + (size_t)r * 128 + c);
                CP_ASYNC16(sKl + o1, gkl + (size_t)r * 128 + c);
                CP_ASYNC16(sVh + o1, gvh + (size_t)r * (Ss * 2) + c);
                CP_ASYNC16(sVl + o1, gvl + (size_t)r * (Ss * 2) + c);
            }
            CP_ASYNC_COMMIT(); CP_ASYNC_WAIT0();
        }
        __syncthreads();

        float acc[8][4];
        #pragma unroll
        for (int nt = 0; nt < 8; nt++)
            #pragma unroll
            for (int r = 0; r < 4; r++) acc[nt][r] = 0.f;

        #pragma unroll
        for (int s = 0; s < 4; s++) {
            uint32_t kB = ((uint32_t)(s * 32) + bkb) ^ xr;
            uint32_t bKh[4][4], bKl[4][4];
            #pragma unroll
            for (int p = 0; p < 4; p++) LDSM4(bKh[p], sKh + boffs[p] + kB);
            #pragma unroll
            for (int p = 0; p < 4; p++) LDSM4(bKl[p], sKl + boffs[p] + kB);
            #pragma unroll
            for (int p = 0; p < 4; p++) {
                MMA16816(acc[2*p],   aQh[s], bKh[p][0], bKh[p][1]);
                MMA16816(acc[2*p+1], aQh[s], bKh[p][2], bKh[p][3]);
                MMA16816(acc[2*p],   aQl[s], bKh[p][0], bKh[p][1]);
                MMA16816(acc[2*p+1], aQl[s], bKh[p][2], bKh[p][3]);
                MMA16816(acc[2*p],   aQh[s], bKl[p][0], bKl[p][1]);
                MMA16816(acc[2*p+1], aQh[s], bKl[p][2], bKl[p][3]);
            }
        }

        const int row0 = q0 + wm + g;
        if (it >= 2 * qt) {
            #pragma unroll
            for (int nt = 0; nt < 8; nt++) {
                int col = kv0 + nt * 8 + tq;
                #pragma unroll
                for (int r = 0; r < 4; r++) {
                    int cc = col + (r & 1);
                    int rr = row0 + (r >= 2 ? 8 : 0);
                    acc[nt][r] = (cc > rr) ? -1e30f : acc[nt][r] * 0.125f;
                }
            }
        } else {
            #pragma unroll
            for (int nt = 0; nt < 8; nt++)
                #pragma unroll
                for (int r = 0; r < 4; r++) acc[nt][r] *= 0.125f;
        }

        #pragma unroll
        for (int h = 0; h < 2; h++) {
            float rmax = -1e30f;
            #pragma unroll
            for (int nt = 0; nt < 8; nt++)
                rmax = fmaxf(rmax, fmaxf(acc[nt][2*h], acc[nt][2*h+1]));
            rmax = fmaxf(rmax, __shfl_xor_sync(0xffffffffu, rmax, 1));
            rmax = fmaxf(rmax, __shfl_xor_sync(0xffffffffu, rmax, 2));
            float mnew = fmaxf(mv[h], rmax);
            float fac = fexp(mv[h] - mnew);
            float rs = 0.f;
            #pragma unroll
            for (int nt = 0; nt < 8; nt++) {
                acc[nt][2*h]   = fexp(acc[nt][2*h]   - mnew);
                acc[nt][2*h+1] = fexp(acc[nt][2*h+1] - mnew);
                rs += acc[nt][2*h] + acc[nt][2*h+1];
            }
            rs += __shfl_xor_sync(0xffffffffu, rs, 1);
            rs += __shfl_xor_sync(0xffffffffu, rs, 2);
            lv[h] = lv[h] * fac + rs;
            mv[h] = mnew;
            #pragma unroll
            for (int nt = 0; nt < 8; nt++) { o[nt][2*h] *= fac; o[nt][2*h+1] *= fac; }
        }

        uint32_t aPh[4][4], aPl[4][4];
        #pragma unroll
        for (int ks = 0; ks < 4; ks++) {
            #pragma unroll
            for (int half = 0; half < 2; half++) {
                int nt = 2 * ks + half;
                #pragma unroll
                for (int rp = 0; rp < 2; rp++) {
                    float p0 = acc[nt][2*rp], p1 = acc[nt][2*rp+1];
                    uint32_t hp = bf2pack(p0, p1);
                    float f0 = __uint_as_float(hp << 16);
                    float f1 = __uint_as_float(hp & 0xFFFF0000u);
                    uint32_t lp = bf2pack(p0 - f0, p1 - f1);
                    aPh[ks][half*2 + rp] = hp;
                    aPl[ks][half*2 + rp] = lp;
                }
            }
        }

        #pragma unroll
        for (int s = 0; s < 4; s++) {
            uint32_t kB = ((uint32_t)(s * 32) + bkb) ^ xr;
            uint32_t bVh[4][4], bVl[4][4];
            #pragma unroll
            for (int p = 0; p < 4; p++) LDSM4(bVh[p], sVh + boffs[p] + kB);
            #pragma unroll
            for (int p = 0; p < 4; p++) LDSM4(bVl[p], sVl + boffs[p] + kB);
            #pragma unroll
            for (int p = 0; p < 4; p++) {
                MMA16816(o[2*p],   aPh[s], bVh[p][0], bVh[p][1]);
                MMA16816(o[2*p+1], aPh[s], bVh[p][2], bVh[p][3]);
                MMA16816(o[2*p],   aPl[s], bVh[p][0], bVh[p][1]);
                MMA16816(o[2*p+1], aPl[s], bVh[p][2], bVh[p][3]);
                MMA16816(o[2*p],   aPh[s], bVl[p][0], bVl[p][1]);
                MMA16816(o[2*p+1], aPh[s], bVl[p][2], bVl[p][3]);
            }
        }
    }

    const int b = bh >> 4, h = bh & 15;
    float il0 = 1.0f / lv[0], il1 = 1.0f / lv[1];
    const int row0 = q0 + wm + g;
    #pragma unroll
    for (int nt = 0; nt < 8; nt++) {
        int col = h * 64 + nt * 8 + tq;
        float2 v0 = make_float2(o[nt][0] * il0, o[nt][1] * il0);
        float2 v1 = make_float2(o[nt][2] * il1, o[nt][3] * il1);
        *(float2*)(out + ((size_t)(b * Ss + row0)) * Ee + col)     = v0;
        *(float2*)(out + ((size_t)(b * Ss + row0 + 8)) * Ee + col) = v1;
    }
}

// ---------------------------------------------------------------------------
extern "C" void kernel_launch(void* const* d_in, const int* in_sizes, int n_in,
                              void* d_out, int out_size)
{
    (void)in_sizes; (void)n_in; (void)out_size;
    const float* query = (const float*)d_in[0];
    const float* key   = (const float*)d_in[1];
    const float* value = (const float*)d_in[2];
    const float* Wq = (const float*)d_in[3];
    const float* bq = (const float*)d_in[4];
    const float* Wk = (const float*)d_in[5];
    const float* bk = (const float*)d_in[6];
    const float* Wv = (const float*)d_in[7];
    const float* bv = (const float*)d_in[8];
    const float* Wo = (const float*)d_in[9];
    const float* bo = (const float*)d_in[10];
    float* out = (float*)d_out;

    float *qp, *kp, *vp, *aop, *ct, *st;
    __nv_bfloat16 *xh, *xl, *wh, *wl, *qh, *ql, *kh, *kl, *vth, *vtl;
    cudaGetSymbolAddress((void**)&qp,  g_q);
    cudaGetSymbolAddress((void**)&kp,  g_k);
    cudaGetSymbolAddress((void**)&vp,  g_v);
    cudaGetSymbolAddress((void**)&aop, g_ao);
    cudaGetSymbolAddress((void**)&ct,  g_cos);
    cudaGetSymbolAddress((void**)&st,  g_sin);
    cudaGetSymbolAddress((void**)&xh,  g_xh3);
    cudaGetSymbolAddress((void**)&xl,  g_xl3);
    cudaGetSymbolAddress((void**)&wh,  g_wh3);
    cudaGetSymbolAddress((void**)&wl,  g_wl3);
    cudaGetSymbolAddress((void**)&qh,  g_qh);
    cudaGetSymbolAddress((void**)&ql,  g_ql);
    cudaGetSymbolAddress((void**)&kh,  g_kh);
    cudaGetSymbolAddress((void**)&kl,  g_kl);
    cudaGetSymbolAddress((void**)&vth, g_vth);
    cudaGetSymbolAddress((void**)&vtl, g_vtl);

    cudaFuncSetAttribute(tgemm_qkv,
                         cudaFuncAttributeMaxDynamicSharedMemorySize, TG_SMEM);
    cudaFuncSetAttribute(tgemm_o,
                         cudaFuncAttributeMaxDynamicSharedMemorySize, TG_SMEM);
    cudaFuncSetAttribute(flash_mma,
                         cudaFuncAttributeMaxDynamicSharedMemorySize, FL_SMEM);

    const int WBLK = (Ee * Ee / 4) / 256;   // 1024
    const int XBLK = (Mm * Ee / 4) / 256;   // 4096
    dim3 gg(Ee / 128, Mm / 128);            // (8, 32)

    rope_table_kernel<<<(Ss * 32) / 256, 256>>>(ct, st);

    // batched splits for QKV phase
    split3_kernel<<<dim3(XBLK, 3), 256>>>(query, key, value, xh, xl, Mm * Ee / 4);
    split3_kernel<<<dim3(WBLK, 3), 256>>>(Wq, Wk, Wv, wh, wl, Ee * Ee / 4);

    // fused QKV projection
    tgemm_qkv<<<dim3(Ee / 128, Mm / 128, 3), 256, TG_SMEM>>>(bq, bk, bv, qp, kp, vp);

    int ropeBlocks = (Bb * Hh * Ss * 8) / 256;   // 2048
    rope_apply_split<<<dim3(ropeBlocks, 2), 256>>>(qp, kp, qh, ql, kh, kl, ct, st);

    vconvert<<<dim3(Ss / 64, Bb * Hh), 256>>>(vp, vth, vtl);

    flash_mma<<<dim3(Ss / 128, Bb * Hh), 256, FL_SMEM>>>(qh, ql, kh, kl, vth, vtl, aop);

    // O projection (slot 0 of triple buffers)
    split_kernel<<<XBLK, 256>>>(aop, xh, xl);
    split_kernel<<<WBLK, 256>>>(Wo, wh, wl);
    tgemm_o<<<gg, 256, TG_SMEM>>>(bo, out);
}